// round 1
// baseline (speedup 1.0000x reference)
#include <cuda_runtime.h>

#define NU 100000
#define NI 50000
#define NV 150000
#define D  64
#define NE 1000000
#define NL 3

// ---------------- static device scratch (no allocations allowed) ----------------
__device__ float d_X[NV * D];     // current layer embeddings [users; items]
__device__ float d_acc[NV * D];   // running sum of layer embeddings
__device__ float d_g[NV * D];     // smoothed embeddings g
__device__ float d_S[NV * D];     // scratch: E (items) at [0..NI), F (users) at [NI..NI+NU)
__device__ int   d_deg_u[NU], d_deg_i[NI];
__device__ float d_du_isqrt[NU], d_du_inv[NU];
__device__ float d_di_isqrt[NI], d_di_inv[NI];
__device__ int   d_rpu[NU + 1], d_rpi[NI + 1];
__device__ int   d_curu[NU], d_curi[NI];
__device__ int   d_colu[NE];      // items, grouped by user
__device__ int   d_coli[NE];      // users, grouped by item

// ---------------- init: copy embeddings, zero degrees ----------------
__global__ void k_init(const float* __restrict__ u_emb, const float* __restrict__ i_emb) {
    int idx = blockIdx.x * blockDim.x + threadIdx.x;
    if (idx < NV * D) {
        float v = (idx < NU * D) ? u_emb[idx] : i_emb[idx - NU * D];
        d_X[idx] = v;
        d_acc[idx] = v;
    }
    if (idx < NU) d_deg_u[idx] = 0;
    if (idx < NI) d_deg_i[idx] = 0;
}

__global__ void k_degree(const int* __restrict__ eu, const int* __restrict__ ei) {
    int e = blockIdx.x * blockDim.x + threadIdx.x;
    if (e < NE) {
        atomicAdd(&d_deg_u[eu[e]], 1);
        atomicAdd(&d_deg_i[ei[e]], 1);
    }
}

__global__ void k_scale() {
    int idx = blockIdx.x * blockDim.x + threadIdx.x;
    if (idx < NU) {
        int dg = d_deg_u[idx];
        d_du_isqrt[idx] = (dg > 0) ? rsqrtf((float)dg) : 0.0f;
        d_du_inv[idx]   = (dg > 0) ? 1.0f / (float)dg : 0.0f;
    }
    if (idx < NI) {
        int dg = d_deg_i[idx];
        d_di_isqrt[idx] = (dg > 0) ? rsqrtf((float)dg) : 0.0f;
        d_di_inv[idx]   = (dg > 0) ? 1.0f / (float)dg : 0.0f;
    }
}

// ---------------- single-block exclusive scan (block 0: users, block 1: items) ----------------
__global__ void k_scan() {
    const int* deg; int* rp; int* cur; int n;
    if (blockIdx.x == 0) { deg = d_deg_u; rp = d_rpu; cur = d_curu; n = NU; }
    else                 { deg = d_deg_i; rp = d_rpi; cur = d_curi; n = NI; }
    __shared__ int swarp[32];
    int tid = threadIdx.x, lane = tid & 31, wid = tid >> 5;
    int carry = 0;
    for (int base = 0; base < n; base += 1024) {
        int idx = base + tid;
        int v = (idx < n) ? deg[idx] : 0;
        int x = v;
        #pragma unroll
        for (int off = 1; off < 32; off <<= 1) {
            int t = __shfl_up_sync(0xffffffffu, x, off);
            if (lane >= off) x += t;
        }
        if (lane == 31) swarp[wid] = x;
        __syncthreads();
        if (wid == 0) {
            int y = swarp[lane];
            #pragma unroll
            for (int off = 1; off < 32; off <<= 1) {
                int t = __shfl_up_sync(0xffffffffu, y, off);
                if (lane >= off) y += t;
            }
            swarp[lane] = y;
        }
        __syncthreads();
        int woff = (wid > 0) ? swarp[wid - 1] : 0;
        int inc = x + woff;
        if (idx < n) {
            int ex = carry + inc - v;
            rp[idx] = ex;
            cur[idx] = ex;
        }
        int total = swarp[31];
        carry += total;
        __syncthreads();
    }
    if (tid == 0) rp[n] = carry;
}

__global__ void k_fill(const int* __restrict__ eu, const int* __restrict__ ei) {
    int e = blockIdx.x * blockDim.x + threadIdx.x;
    if (e < NE) {
        int u = eu[e], it = ei[e];
        int pu = atomicAdd(&d_curu[u], 1);
        d_colu[pu] = it;
        int pi = atomicAdd(&d_curi[it], 1);
        d_coli[pi] = u;
    }
}

// ---------------- smoothing pass 1: E[i] (items) and F[u] (users), warp per vertex ----------------
__global__ void k_smoothA() {
    int w = (blockIdx.x * blockDim.x + threadIdx.x) >> 5;
    int lane = threadIdx.x & 31;
    const float2* __restrict__ X2 = (const float2*)d_X;
    float2* __restrict__ S2 = (float2*)d_S;

    if (w < NI) {
        int v = w;
        int s = d_rpi[v], e = d_rpi[v + 1];
        float2 a0 = make_float2(0.f, 0.f), a1 = make_float2(0.f, 0.f);
        int p = s;
        for (; p + 1 < e; p += 2) {
            int u0 = __ldg(&d_coli[p]);
            int u1 = __ldg(&d_coli[p + 1]);
            float w0 = __ldg(&d_du_isqrt[u0]);
            float w1 = __ldg(&d_du_isqrt[u1]);
            float2 x0 = __ldg(&X2[u0 * 32 + lane]);
            float2 x1 = __ldg(&X2[u1 * 32 + lane]);
            a0.x += w0 * x0.x; a0.y += w0 * x0.y;
            a1.x += w1 * x1.x; a1.y += w1 * x1.y;
        }
        if (p < e) {
            int u0 = __ldg(&d_coli[p]);
            float w0 = __ldg(&d_du_isqrt[u0]);
            float2 x0 = __ldg(&X2[u0 * 32 + lane]);
            a0.x += w0 * x0.x; a0.y += w0 * x0.y;
        }
        float sc = d_di_inv[v];
        S2[v * 32 + lane] = make_float2(sc * (a0.x + a1.x), sc * (a0.y + a1.y));
    } else if (w < NI + NU) {
        int v = w - NI;
        int s = d_rpu[v], e = d_rpu[v + 1];
        float2 a0 = make_float2(0.f, 0.f), a1 = make_float2(0.f, 0.f);
        int p = s;
        for (; p + 1 < e; p += 2) {
            int i0 = __ldg(&d_colu[p]);
            int i1 = __ldg(&d_colu[p + 1]);
            float w0 = __ldg(&d_di_isqrt[i0]);
            float w1 = __ldg(&d_di_isqrt[i1]);
            float2 x0 = __ldg(&X2[(NU + i0) * 32 + lane]);
            float2 x1 = __ldg(&X2[(NU + i1) * 32 + lane]);
            a0.x += w0 * x0.x; a0.y += w0 * x0.y;
            a1.x += w1 * x1.x; a1.y += w1 * x1.y;
        }
        if (p < e) {
            int i0 = __ldg(&d_colu[p]);
            float w0 = __ldg(&d_di_isqrt[i0]);
            float2 x0 = __ldg(&X2[(NU + i0) * 32 + lane]);
            a0.x += w0 * x0.x; a0.y += w0 * x0.y;
        }
        float sc = d_du_inv[v];
        S2[(NI + v) * 32 + lane] = make_float2(sc * (a0.x + a1.x), sc * (a0.y + a1.y));
    }
}

// ---------------- smoothing pass 2: g[u] from E, g[NU+i] from F ----------------
__global__ void k_smoothB() {
    int w = (blockIdx.x * blockDim.x + threadIdx.x) >> 5;
    int lane = threadIdx.x & 31;
    const float2* __restrict__ S2 = (const float2*)d_S;
    float2* __restrict__ G2 = (float2*)d_g;

    if (w < NU) {
        int v = w;
        int s = d_rpu[v], e = d_rpu[v + 1];
        float2 a0 = make_float2(0.f, 0.f), a1 = make_float2(0.f, 0.f);
        int p = s;
        for (; p + 1 < e; p += 2) {
            int i0 = __ldg(&d_colu[p]);
            int i1 = __ldg(&d_colu[p + 1]);
            float2 x0 = __ldg(&S2[i0 * 32 + lane]);
            float2 x1 = __ldg(&S2[i1 * 32 + lane]);
            a0.x += x0.x; a0.y += x0.y;
            a1.x += x1.x; a1.y += x1.y;
        }
        if (p < e) {
            int i0 = __ldg(&d_colu[p]);
            float2 x0 = __ldg(&S2[i0 * 32 + lane]);
            a0.x += x0.x; a0.y += x0.y;
        }
        float sc = d_du_isqrt[v];
        G2[v * 32 + lane] = make_float2(sc * (a0.x + a1.x), sc * (a0.y + a1.y));
    } else if (w < NU + NI) {
        int v = w - NU;
        int s = d_rpi[v], e = d_rpi[v + 1];
        float2 a0 = make_float2(0.f, 0.f), a1 = make_float2(0.f, 0.f);
        int p = s;
        for (; p + 1 < e; p += 2) {
            int u0 = __ldg(&d_coli[p]);
            int u1 = __ldg(&d_coli[p + 1]);
            float2 x0 = __ldg(&S2[(NI + u0) * 32 + lane]);
            float2 x1 = __ldg(&S2[(NI + u1) * 32 + lane]);
            a0.x += x0.x; a0.y += x0.y;
            a1.x += x1.x; a1.y += x1.y;
        }
        if (p < e) {
            int u0 = __ldg(&d_coli[p]);
            float2 x0 = __ldg(&S2[(NI + u0) * 32 + lane]);
            a0.x += x0.x; a0.y += x0.y;
        }
        float sc = d_di_isqrt[v];
        G2[(NU + v) * 32 + lane] = make_float2(sc * (a0.x + a1.x), sc * (a0.y + a1.y));
    }
}

// ---------------- fused layer update: dual GEMM + bias + leakyReLU + residual + L2 norm + accumulate ----------------
// out_g = leaky(g @ Wgc^T + bgc + X); out_b = leaky((X*g) @ Wbi^T + bbi); Xn = normalize(out_g+out_b); acc += Xn
#define SMEM_FLOATS (4160 + 4160 + 4096 + 4096 + 64 + 64)
__global__ void k_layer(const float* __restrict__ Wgc, const float* __restrict__ bgc,
                        const float* __restrict__ Wbi, const float* __restrict__ bbi, int l) {
    extern __shared__ float sh[];
    float* sG  = sh;              // [64][65]
    float* sX  = sh + 4160;       // [64][65]
    float* sWg = sh + 8320;       // Wt[k][d]  [64][64]
    float* sWb = sh + 12416;      // [64][64]
    float* sbg = sh + 16512;      // [64]
    float* sbb = sh + 16576;      // [64]

    int t = threadIdx.x;                  // 256 threads
    int row0 = blockIdx.x * 64;

    // load W transposed (Wt[k][d] = W[d][k]) and biases
    const float* Wg = Wgc + l * 4096;
    const float* Wb = Wbi + l * 4096;
    #pragma unroll
    for (int i = t; i < 4096; i += 256) {
        int k = i >> 6, d = i & 63;
        sWg[k * 64 + d] = __ldg(&Wg[d * 64 + k]);
        sWb[k * 64 + d] = __ldg(&Wb[d * 64 + k]);
    }
    if (t < 64) {
        sbg[t] = bgc[l * 64 + t];
        sbb[t] = bbi[l * 64 + t];
    }
    // load G and X tiles (row-major, pad 65)
    #pragma unroll
    for (int i = t; i < 4096; i += 256) {
        int r = i >> 6, k = i & 63;
        int gr = row0 + r;
        float gv = 0.f, xv = 0.f;
        if (gr < NV) { gv = d_g[gr * 64 + k]; xv = d_X[gr * 64 + k]; }
        sG[r * 65 + k] = gv;
        sX[r * 65 + k] = xv;
    }
    __syncthreads();

    int tx = t & 15, ty = t >> 4;
    int c0 = tx * 4, r0 = ty * 4;
    float ag[4][4] = {}, ab[4][4] = {};

    #pragma unroll 8
    for (int k = 0; k < 64; k++) {
        float4 wg = *(const float4*)&sWg[k * 64 + c0];
        float4 wb = *(const float4*)&sWb[k * 64 + c0];
        #pragma unroll
        for (int i = 0; i < 4; i++) {
            float gv = sG[(r0 + i) * 65 + k];
            float xv = sX[(r0 + i) * 65 + k];
            float hv = gv * xv;
            ag[i][0] += gv * wg.x; ag[i][1] += gv * wg.y; ag[i][2] += gv * wg.z; ag[i][3] += gv * wg.w;
            ab[i][0] += hv * wb.x; ab[i][1] += hv * wb.y; ab[i][2] += hv * wb.z; ab[i][3] += hv * wb.w;
        }
    }

    #pragma unroll
    for (int i = 0; i < 4; i++) {
        float vj[4];
        float ssq = 0.f;
        #pragma unroll
        for (int j = 0; j < 4; j++) {
            float sg = ag[i][j] + sbg[c0 + j] + sX[(r0 + i) * 65 + (c0 + j)];
            sg = (sg > 0.f) ? sg : 0.2f * sg;
            float sb = ab[i][j] + sbb[c0 + j];
            sb = (sb > 0.f) ? sb : 0.2f * sb;
            float v = sg + sb;
            vj[j] = v;
            ssq += v * v;
        }
        // reduce across the 16 tx threads (low 4 lane bits)
        #pragma unroll
        for (int m = 8; m >= 1; m >>= 1)
            ssq += __shfl_xor_sync(0xffffffffu, ssq, m);
        float inv = 1.0f / fmaxf(sqrtf(ssq), 1e-12f);
        int gr = row0 + r0 + i;
        if (gr < NV) {
            float4 o;
            o.x = vj[0] * inv; o.y = vj[1] * inv; o.z = vj[2] * inv; o.w = vj[3] * inv;
            *(float4*)&d_X[gr * 64 + c0] = o;
            float4 a = *(float4*)&d_acc[gr * 64 + c0];
            a.x += o.x; a.y += o.y; a.z += o.z; a.w += o.w;
            *(float4*)&d_acc[gr * 64 + c0] = a;
        }
    }
}

__global__ void k_out(float* __restrict__ out) {
    int idx = blockIdx.x * blockDim.x + threadIdx.x;
    if (idx < NV * D) out[idx] = d_acc[idx] * 0.25f;
}

// ---------------- launch ----------------
extern "C" void kernel_launch(void* const* d_in, const int* in_sizes, int n_in,
                              void* d_out, int out_size) {
    const float* u_emb = (const float*)d_in[0];
    const float* i_emb = (const float*)d_in[1];
    const float* Wgc   = (const float*)d_in[2];
    const float* bgc   = (const float*)d_in[3];
    const float* Wbi   = (const float*)d_in[4];
    const float* bbi   = (const float*)d_in[5];
    const int*   eu    = (const int*)d_in[6];
    const int*   ei    = (const int*)d_in[7];
    float* out = (float*)d_out;

    cudaFuncSetAttribute(k_layer, cudaFuncAttributeMaxDynamicSharedMemorySize,
                         SMEM_FLOATS * (int)sizeof(float));

    k_init<<<(NV * D + 255) / 256, 256>>>(u_emb, i_emb);
    k_degree<<<(NE + 255) / 256, 256>>>(eu, ei);
    k_scale<<<(NU + 255) / 256, 256>>>();
    k_scan<<<2, 1024>>>();
    k_fill<<<(NE + 255) / 256, 256>>>(eu, ei);

    for (int l = 0; l < NL; l++) {
        k_smoothA<<<(NV * 32 + 255) / 256, 256>>>();
        k_smoothB<<<(NV * 32 + 255) / 256, 256>>>();
        k_layer<<<(NV + 63) / 64, 256, SMEM_FLOATS * (int)sizeof(float)>>>(Wgc, bgc, Wbi, bbi, l);
    }

    k_out<<<(NV * D + 255) / 256, 256>>>(out);
}

// round 2
// speedup vs baseline: 1.0770x; 1.0770x over previous
#include <cuda_runtime.h>

#define NU 100000
#define NI 50000
#define NV 150000
#define D  64
#define NE 1000000
#define NL 3

#define CHUNK 1024
#define PBU ((NU + CHUNK - 1) / CHUNK)   // 98
#define PBI ((NI + CHUNK - 1) / CHUNK)   // 49
#define NPART (PBU + PBI)                // 147

// ---------------- static device scratch ----------------
__device__ float d_X[NV * D];     // current layer embeddings [users; items]
__device__ float d_Xs[NV * D];    // X pre-scaled rowwise by dv_isqrt
__device__ float d_acc[NV * D];   // running sum of layer embeddings
__device__ float d_g[NV * D];     // smoothed embeddings g
__device__ float d_S[NV * D];     // scratch: E (items) at [0..NI), F (users) at [NI..NV)
__device__ int   d_deg_u[NU], d_deg_i[NI];
__device__ float d_du_isqrt[NU], d_du_inv[NU];
__device__ float d_di_isqrt[NI], d_di_inv[NI];
__device__ int   d_rpu[NU + 1], d_rpi[NI + 1];
__device__ int   d_curu[NU], d_curi[NI];
__device__ int   d_colu[NE];      // items, grouped by user
__device__ int   d_coli[NE];      // users, grouped by item
__device__ int   d_part[256];     // block partial sums for scan

// ---------------- init: copy embeddings, zero degrees ----------------
__global__ void k_init(const float* __restrict__ u_emb, const float* __restrict__ i_emb) {
    int idx = blockIdx.x * blockDim.x + threadIdx.x;
    if (idx < NV * D) {
        float v = (idx < NU * D) ? u_emb[idx] : i_emb[idx - NU * D];
        d_X[idx] = v;
        d_acc[idx] = v;
    }
    if (idx < NU) d_deg_u[idx] = 0;
    if (idx < NI) d_deg_i[idx] = 0;
}

__global__ void k_degree(const int* __restrict__ eu, const int* __restrict__ ei) {
    int e = blockIdx.x * blockDim.x + threadIdx.x;
    if (e < NE) {
        atomicAdd(&d_deg_u[eu[e]], 1);
        atomicAdd(&d_deg_i[ei[e]], 1);
    }
}

// ---------------- 3-phase scan ----------------
// phase 1: per-chunk sums (blocks 0..PBU-1: users, PBU..NPART-1: items)
__global__ void k_part() {
    int b = blockIdx.x;
    const int* deg; int n; int cb;
    if (b < PBU) { deg = d_deg_u; n = NU; cb = b; }
    else         { deg = d_deg_i; n = NI; cb = b - PBU; }
    int base = cb * CHUNK;
    int t = threadIdx.x;             // 256 threads, 4 elems each
    int tsum = 0;
    #pragma unroll
    for (int j = 0; j < 4; j++) {
        int idx = base + t * 4 + j;
        if (idx < n) tsum += deg[idx];
    }
    // warp + block reduce
    #pragma unroll
    for (int m = 16; m >= 1; m >>= 1) tsum += __shfl_xor_sync(0xffffffffu, tsum, m);
    __shared__ int sw[8];
    if ((t & 31) == 0) sw[t >> 5] = tsum;
    __syncthreads();
    if (t == 0) {
        int s = 0;
        #pragma unroll
        for (int w = 0; w < 8; w++) s += sw[w];
        d_part[b] = s;
    }
}

// phase 2: segmented exclusive scan of the 147 partials (1 block)
__global__ void k_spine() {
    __shared__ int s[256];
    int t = threadIdx.x;
    int v = (t < NPART) ? d_part[t] : 0;
    s[t] = v;
    __syncthreads();
    #pragma unroll
    for (int off = 1; off < 256; off <<= 1) {
        int add = 0;
        if (t >= off && (((t - off) >= PBU) == (t >= PBU))) add = s[t - off];
        __syncthreads();
        s[t] += add;
        __syncthreads();
    }
    if (t < NPART) d_part[t] = s[t] - v;   // segment-exclusive
    if (t == PBU - 1)   d_rpu[NU] = s[t];
    if (t == NPART - 1) d_rpi[NI] = s[t];
}

// phase 3: downsweep -> rp, cur, and the degree-derived scales
__global__ void k_down() {
    int b = blockIdx.x;
    const int* deg; int* rp; int* cur; float* isq; float* inv; int n; int cb;
    if (b < PBU) { deg = d_deg_u; rp = d_rpu; cur = d_curu; isq = d_du_isqrt; inv = d_du_inv; n = NU; cb = b; }
    else         { deg = d_deg_i; rp = d_rpi; cur = d_curi; isq = d_di_isqrt; inv = d_di_inv; n = NI; cb = b - PBU; }
    int base = cb * CHUNK;
    int t = threadIdx.x;
    int idx0 = base + t * 4;
    int v[4]; int tsum = 0;
    #pragma unroll
    for (int j = 0; j < 4; j++) {
        v[j] = (idx0 + j < n) ? deg[idx0 + j] : 0;
        tsum += v[j];
    }
    __shared__ int s[256];
    s[t] = tsum;
    __syncthreads();
    #pragma unroll
    for (int off = 1; off < 256; off <<= 1) {
        int add = (t >= off) ? s[t - off] : 0;
        __syncthreads();
        s[t] += add;
        __syncthreads();
    }
    int off0 = d_part[b] + (s[t] - tsum);
    int run = 0;
    #pragma unroll
    for (int j = 0; j < 4; j++) {
        int idx = idx0 + j;
        if (idx < n) {
            rp[idx] = off0 + run;
            cur[idx] = off0 + run;
            int dg = v[j];
            isq[idx] = (dg > 0) ? rsqrtf((float)dg) : 0.0f;
            inv[idx] = (dg > 0) ? 1.0f / (float)dg : 0.0f;
            run += dg;
        }
    }
}

__global__ void k_fill(const int* __restrict__ eu, const int* __restrict__ ei) {
    int e = blockIdx.x * blockDim.x + threadIdx.x;
    if (e < NE) {
        int u = eu[e], it = ei[e];
        int pu = atomicAdd(&d_curu[u], 1);
        d_colu[pu] = it;
        int pi = atomicAdd(&d_curi[it], 1);
        d_coli[pi] = u;
    }
}

// ---------------- prescale: Xs = X * dv_isqrt (layer 0 only; layers 1-2 fused into k_layer) ----------------
__global__ void k_prescale() {
    int gt = blockIdx.x * blockDim.x + threadIdx.x;
    if (gt < NV * 16) {
        int r = gt >> 4;
        float s = (r < NU) ? d_du_isqrt[r] : d_di_isqrt[r - NU];
        float4 x = ((const float4*)d_X)[gt];
        x.x *= s; x.y *= s; x.z *= s; x.w *= s;
        ((float4*)d_Xs)[gt] = x;
    }
}

// ---------------- smoothing pass 1 (half-warp per vertex, float4 rows) ----------------
// items: S[v] = di_inv[v] * sum_{u in coli[v]} Xs[u]
// users: S[NI+v] = du_inv[v] * sum_{i in colu[v]} Xs[NU+i]
__global__ void k_smoothA() {
    int gt = blockIdx.x * blockDim.x + threadIdx.x;
    int hw = gt >> 4, lane = gt & 15;
    const float4* __restrict__ Xs4 = (const float4*)d_Xs;
    float4* __restrict__ S4 = (float4*)d_S;

    if (hw < NI) {
        int v = hw;
        int s = d_rpi[v], e = d_rpi[v + 1];
        float4 a0 = {0,0,0,0}, a1 = {0,0,0,0};
        int p = s;
        for (; p + 1 < e; p += 2) {
            int u0 = __ldg(&d_coli[p]);
            int u1 = __ldg(&d_coli[p + 1]);
            float4 x0 = __ldg(&Xs4[u0 * 16 + lane]);
            float4 x1 = __ldg(&Xs4[u1 * 16 + lane]);
            a0.x += x0.x; a0.y += x0.y; a0.z += x0.z; a0.w += x0.w;
            a1.x += x1.x; a1.y += x1.y; a1.z += x1.z; a1.w += x1.w;
        }
        if (p < e) {
            int u0 = __ldg(&d_coli[p]);
            float4 x0 = __ldg(&Xs4[u0 * 16 + lane]);
            a0.x += x0.x; a0.y += x0.y; a0.z += x0.z; a0.w += x0.w;
        }
        float sc = d_di_inv[v];
        float4 o;
        o.x = sc * (a0.x + a1.x); o.y = sc * (a0.y + a1.y);
        o.z = sc * (a0.z + a1.z); o.w = sc * (a0.w + a1.w);
        S4[v * 16 + lane] = o;
    } else if (hw < NV) {
        int v = hw - NI;
        int s = d_rpu[v], e = d_rpu[v + 1];
        float4 a0 = {0,0,0,0}, a1 = {0,0,0,0};
        int p = s;
        for (; p + 1 < e; p += 2) {
            int i0 = __ldg(&d_colu[p]);
            int i1 = __ldg(&d_colu[p + 1]);
            float4 x0 = __ldg(&Xs4[(NU + i0) * 16 + lane]);
            float4 x1 = __ldg(&Xs4[(NU + i1) * 16 + lane]);
            a0.x += x0.x; a0.y += x0.y; a0.z += x0.z; a0.w += x0.w;
            a1.x += x1.x; a1.y += x1.y; a1.z += x1.z; a1.w += x1.w;
        }
        if (p < e) {
            int i0 = __ldg(&d_colu[p]);
            float4 x0 = __ldg(&Xs4[(NU + i0) * 16 + lane]);
            a0.x += x0.x; a0.y += x0.y; a0.z += x0.z; a0.w += x0.w;
        }
        float sc = d_du_inv[v];
        float4 o;
        o.x = sc * (a0.x + a1.x); o.y = sc * (a0.y + a1.y);
        o.z = sc * (a0.z + a1.z); o.w = sc * (a0.w + a1.w);
        S4[(NI + v) * 16 + lane] = o;
    }
}

// ---------------- smoothing pass 2 ----------------
// users: g[v]    = du_isqrt[v] * sum_{i in colu[v]} S[i]
// items: g[NU+v] = di_isqrt[v] * sum_{u in coli[v]} S[NI+u]
__global__ void k_smoothB() {
    int gt = blockIdx.x * blockDim.x + threadIdx.x;
    int hw = gt >> 4, lane = gt & 15;
    const float4* __restrict__ S4 = (const float4*)d_S;
    float4* __restrict__ G4 = (float4*)d_g;

    if (hw < NU) {
        int v = hw;
        int s = d_rpu[v], e = d_rpu[v + 1];
        float4 a0 = {0,0,0,0}, a1 = {0,0,0,0};
        int p = s;
        for (; p + 1 < e; p += 2) {
            int i0 = __ldg(&d_colu[p]);
            int i1 = __ldg(&d_colu[p + 1]);
            float4 x0 = __ldg(&S4[i0 * 16 + lane]);
            float4 x1 = __ldg(&S4[i1 * 16 + lane]);
            a0.x += x0.x; a0.y += x0.y; a0.z += x0.z; a0.w += x0.w;
            a1.x += x1.x; a1.y += x1.y; a1.z += x1.z; a1.w += x1.w;
        }
        if (p < e) {
            int i0 = __ldg(&d_colu[p]);
            float4 x0 = __ldg(&S4[i0 * 16 + lane]);
            a0.x += x0.x; a0.y += x0.y; a0.z += x0.z; a0.w += x0.w;
        }
        float sc = d_du_isqrt[v];
        float4 o;
        o.x = sc * (a0.x + a1.x); o.y = sc * (a0.y + a1.y);
        o.z = sc * (a0.z + a1.z); o.w = sc * (a0.w + a1.w);
        G4[v * 16 + lane] = o;
    } else if (hw < NV) {
        int v = hw - NU;
        int s = d_rpi[v], e = d_rpi[v + 1];
        float4 a0 = {0,0,0,0}, a1 = {0,0,0,0};
        int p = s;
        for (; p + 1 < e; p += 2) {
            int u0 = __ldg(&d_coli[p]);
            int u1 = __ldg(&d_coli[p + 1]);
            float4 x0 = __ldg(&S4[(NI + u0) * 16 + lane]);
            float4 x1 = __ldg(&S4[(NI + u1) * 16 + lane]);
            a0.x += x0.x; a0.y += x0.y; a0.z += x0.z; a0.w += x0.w;
            a1.x += x1.x; a1.y += x1.y; a1.z += x1.z; a1.w += x1.w;
        }
        if (p < e) {
            int u0 = __ldg(&d_coli[p]);
            float4 x0 = __ldg(&S4[(NI + u0) * 16 + lane]);
            a0.x += x0.x; a0.y += x0.y; a0.z += x0.z; a0.w += x0.w;
        }
        float sc = d_di_isqrt[v];
        float4 o;
        o.x = sc * (a0.x + a1.x); o.y = sc * (a0.y + a1.y);
        o.z = sc * (a0.z + a1.z); o.w = sc * (a0.w + a1.w);
        G4[(NU + v) * 16 + lane] = o;
    }
}

// ---------------- fused layer update ----------------
// out_g = leaky(g @ Wgc^T + bgc + X); out_b = leaky((X*g) @ Wbi^T + bbi)
// Xn = normalize(out_g + out_b); acc += Xn; Xs = Xn * dv_isqrt (if write_xs)
#define SMEM_FLOATS (4160 + 4160 + 4096 + 4096 + 64 + 64)
__global__ void k_layer(const float* __restrict__ Wgc, const float* __restrict__ bgc,
                        const float* __restrict__ Wbi, const float* __restrict__ bbi,
                        int l, int write_xs) {
    extern __shared__ float sh[];
    float* sG  = sh;              // [64][65]
    float* sX  = sh + 4160;       // [64][65]
    float* sWg = sh + 8320;       // Wt[k][d]
    float* sWb = sh + 12416;
    float* sbg = sh + 16512;
    float* sbb = sh + 16576;

    int t = threadIdx.x;          // 256 threads
    int row0 = blockIdx.x * 64;

    const float* Wg = Wgc + l * 4096;
    const float* Wb = Wbi + l * 4096;
    #pragma unroll
    for (int i = t; i < 4096; i += 256) {
        int k = i >> 6, d = i & 63;
        sWg[k * 64 + d] = __ldg(&Wg[d * 64 + k]);
        sWb[k * 64 + d] = __ldg(&Wb[d * 64 + k]);
    }
    if (t < 64) {
        sbg[t] = bgc[l * 64 + t];
        sbb[t] = bbi[l * 64 + t];
    }
    #pragma unroll
    for (int i = t; i < 4096; i += 256) {
        int r = i >> 6, k = i & 63;
        int gr = row0 + r;
        float gv = 0.f, xv = 0.f;
        if (gr < NV) { gv = d_g[gr * 64 + k]; xv = d_X[gr * 64 + k]; }
        sG[r * 65 + k] = gv;
        sX[r * 65 + k] = xv;
    }
    __syncthreads();

    int tx = t & 15, ty = t >> 4;
    int c0 = tx * 4, r0 = ty * 4;
    float ag[4][4] = {}, ab[4][4] = {};

    #pragma unroll 8
    for (int k = 0; k < 64; k++) {
        float4 wg = *(const float4*)&sWg[k * 64 + c0];
        float4 wb = *(const float4*)&sWb[k * 64 + c0];
        #pragma unroll
        for (int i = 0; i < 4; i++) {
            float gv = sG[(r0 + i) * 65 + k];
            float xv = sX[(r0 + i) * 65 + k];
            float hv = gv * xv;
            ag[i][0] += gv * wg.x; ag[i][1] += gv * wg.y; ag[i][2] += gv * wg.z; ag[i][3] += gv * wg.w;
            ab[i][0] += hv * wb.x; ab[i][1] += hv * wb.y; ab[i][2] += hv * wb.z; ab[i][3] += hv * wb.w;
        }
    }

    #pragma unroll
    for (int i = 0; i < 4; i++) {
        float vj[4];
        float ssq = 0.f;
        #pragma unroll
        for (int j = 0; j < 4; j++) {
            float sg = ag[i][j] + sbg[c0 + j] + sX[(r0 + i) * 65 + (c0 + j)];
            sg = (sg > 0.f) ? sg : 0.2f * sg;
            float sb = ab[i][j] + sbb[c0 + j];
            sb = (sb > 0.f) ? sb : 0.2f * sb;
            float v = sg + sb;
            vj[j] = v;
            ssq += v * v;
        }
        #pragma unroll
        for (int m = 8; m >= 1; m >>= 1)
            ssq += __shfl_xor_sync(0xffffffffu, ssq, m);
        float inv = 1.0f / fmaxf(sqrtf(ssq), 1e-12f);
        int gr = row0 + r0 + i;
        if (gr < NV) {
            float4 o;
            o.x = vj[0] * inv; o.y = vj[1] * inv; o.z = vj[2] * inv; o.w = vj[3] * inv;
            *(float4*)&d_X[gr * 64 + c0] = o;
            float4 a = *(float4*)&d_acc[gr * 64 + c0];
            a.x += o.x; a.y += o.y; a.z += o.z; a.w += o.w;
            *(float4*)&d_acc[gr * 64 + c0] = a;
            if (write_xs) {
                float srow = (gr < NU) ? d_du_isqrt[gr] : d_di_isqrt[gr - NU];
                float4 xs;
                xs.x = o.x * srow; xs.y = o.y * srow; xs.z = o.z * srow; xs.w = o.w * srow;
                *(float4*)&d_Xs[gr * 64 + c0] = xs;
            }
        }
    }
}

__global__ void k_out(float* __restrict__ out) {
    int idx = blockIdx.x * blockDim.x + threadIdx.x;
    if (idx < NV * D) out[idx] = d_acc[idx] * 0.25f;
}

// ---------------- launch ----------------
extern "C" void kernel_launch(void* const* d_in, const int* in_sizes, int n_in,
                              void* d_out, int out_size) {
    const float* u_emb = (const float*)d_in[0];
    const float* i_emb = (const float*)d_in[1];
    const float* Wgc   = (const float*)d_in[2];
    const float* bgc   = (const float*)d_in[3];
    const float* Wbi   = (const float*)d_in[4];
    const float* bbi   = (const float*)d_in[5];
    const int*   eu    = (const int*)d_in[6];
    const int*   ei    = (const int*)d_in[7];
    float* out = (float*)d_out;

    cudaFuncSetAttribute(k_layer, cudaFuncAttributeMaxDynamicSharedMemorySize,
                         SMEM_FLOATS * (int)sizeof(float));

    k_init<<<(NV * D + 255) / 256, 256>>>(u_emb, i_emb);
    k_degree<<<(NE + 255) / 256, 256>>>(eu, ei);
    k_part<<<NPART, 256>>>();
    k_spine<<<1, 256>>>();
    k_down<<<NPART, 256>>>();
    k_fill<<<(NE + 255) / 256, 256>>>(eu, ei);
    k_prescale<<<(NV * 16 + 255) / 256, 256>>>();

    for (int l = 0; l < NL; l++) {
        k_smoothA<<<(NV * 16 + 255) / 256, 256>>>();
        k_smoothB<<<(NV * 16 + 255) / 256, 256>>>();
        k_layer<<<(NV + 63) / 64, 256, SMEM_FLOATS * (int)sizeof(float)>>>(
            Wgc, bgc, Wbi, bbi, l, (l < NL - 1) ? 1 : 0);
    }

    k_out<<<(NV * D + 255) / 256, 256>>>(out);
}

// round 3
// speedup vs baseline: 1.1232x; 1.0428x over previous
#include <cuda_runtime.h>
#include <cuda_fp16.h>

#define NU 100000
#define NI 50000
#define NV 150000
#define D  64
#define NE 1000000
#define NL 3

#define CHUNK 1024
#define PBU ((NU + CHUNK - 1) / CHUNK)   // 98
#define PBI ((NI + CHUNK - 1) / CHUNK)   // 49
#define NPART (PBU + PBI)                // 147

// ---------------- static device scratch ----------------
__device__ float d_X[NV * D];     // current layer embeddings [users; items] (fp32)
__device__ float d_acc[NV * D];   // running sum of layer embeddings
__device__ float d_g[NV * D];     // smoothed embeddings g (fp32)
__device__ uint2 d_Xh[NV * 16];   // X pre-scaled by dv_isqrt, fp16 rows (64 half = 16 uint2)
__device__ uint2 d_Sh[NV * 16];   // mid-hop scratch, fp16: E(items) [0..NI), F(users) [NI..NV)
__device__ int   d_deg_u[NU], d_deg_i[NI];
__device__ float d_du_isqrt[NU], d_du_inv[NU];
__device__ float d_di_isqrt[NI], d_di_inv[NI];
__device__ int   d_rpu[NU + 1], d_rpi[NI + 1];
__device__ int   d_curu[NU], d_curi[NI];
__device__ int   d_colu[NE];      // items, grouped by user
__device__ int   d_coli[NE];      // users, grouped by item
__device__ int   d_part[256];     // block partial sums for scan

// ---------------- helpers ----------------
__device__ __forceinline__ float4 h4_to_f4(uint2 q) {
    __half2 h0 = *(__half2*)&q.x;
    __half2 h1 = *(__half2*)&q.y;
    float2 f0 = __half22float2(h0);
    float2 f1 = __half22float2(h1);
    return make_float4(f0.x, f0.y, f1.x, f1.y);
}
__device__ __forceinline__ uint2 f4_to_h4(float4 f) {
    __half2 h0 = __floats2half2_rn(f.x, f.y);
    __half2 h1 = __floats2half2_rn(f.z, f.w);
    uint2 q;
    q.x = *(unsigned*)&h0;
    q.y = *(unsigned*)&h1;
    return q;
}

// ---------------- init: copy embeddings, zero degrees ----------------
__global__ void k_init(const float* __restrict__ u_emb, const float* __restrict__ i_emb) {
    int idx = blockIdx.x * blockDim.x + threadIdx.x;
    if (idx < NV * D) {
        float v = (idx < NU * D) ? u_emb[idx] : i_emb[idx - NU * D];
        d_X[idx] = v;
        d_acc[idx] = v;
    }
    if (idx < NU) d_deg_u[idx] = 0;
    if (idx < NI) d_deg_i[idx] = 0;
}

__global__ void k_degree(const int* __restrict__ eu, const int* __restrict__ ei) {
    int e = blockIdx.x * blockDim.x + threadIdx.x;
    if (e < NE) {
        atomicAdd(&d_deg_u[eu[e]], 1);
        atomicAdd(&d_deg_i[ei[e]], 1);
    }
}

// ---------------- 3-phase scan ----------------
__global__ void k_part() {
    int b = blockIdx.x;
    const int* deg; int n; int cb;
    if (b < PBU) { deg = d_deg_u; n = NU; cb = b; }
    else         { deg = d_deg_i; n = NI; cb = b - PBU; }
    int base = cb * CHUNK;
    int t = threadIdx.x;
    int tsum = 0;
    #pragma unroll
    for (int j = 0; j < 4; j++) {
        int idx = base + t * 4 + j;
        if (idx < n) tsum += deg[idx];
    }
    #pragma unroll
    for (int m = 16; m >= 1; m >>= 1) tsum += __shfl_xor_sync(0xffffffffu, tsum, m);
    __shared__ int sw[8];
    if ((t & 31) == 0) sw[t >> 5] = tsum;
    __syncthreads();
    if (t == 0) {
        int s = 0;
        #pragma unroll
        for (int w = 0; w < 8; w++) s += sw[w];
        d_part[b] = s;
    }
}

__global__ void k_spine() {
    __shared__ int s[256];
    int t = threadIdx.x;
    int v = (t < NPART) ? d_part[t] : 0;
    s[t] = v;
    __syncthreads();
    #pragma unroll
    for (int off = 1; off < 256; off <<= 1) {
        int add = 0;
        if (t >= off && (((t - off) >= PBU) == (t >= PBU))) add = s[t - off];
        __syncthreads();
        s[t] += add;
        __syncthreads();
    }
    if (t < NPART) d_part[t] = s[t] - v;
    if (t == PBU - 1)   d_rpu[NU] = s[t];
    if (t == NPART - 1) d_rpi[NI] = s[t];
}

__global__ void k_down() {
    int b = blockIdx.x;
    const int* deg; int* rp; int* cur; float* isq; float* inv; int n; int cb;
    if (b < PBU) { deg = d_deg_u; rp = d_rpu; cur = d_curu; isq = d_du_isqrt; inv = d_du_inv; n = NU; cb = b; }
    else         { deg = d_deg_i; rp = d_rpi; cur = d_curi; isq = d_di_isqrt; inv = d_di_inv; n = NI; cb = b - PBU; }
    int base = cb * CHUNK;
    int t = threadIdx.x;
    int idx0 = base + t * 4;
    int v[4]; int tsum = 0;
    #pragma unroll
    for (int j = 0; j < 4; j++) {
        v[j] = (idx0 + j < n) ? deg[idx0 + j] : 0;
        tsum += v[j];
    }
    __shared__ int s[256];
    s[t] = tsum;
    __syncthreads();
    #pragma unroll
    for (int off = 1; off < 256; off <<= 1) {
        int add = (t >= off) ? s[t - off] : 0;
        __syncthreads();
        s[t] += add;
        __syncthreads();
    }
    int off0 = d_part[b] + (s[t] - tsum);
    int run = 0;
    #pragma unroll
    for (int j = 0; j < 4; j++) {
        int idx = idx0 + j;
        if (idx < n) {
            rp[idx] = off0 + run;
            cur[idx] = off0 + run;
            int dg = v[j];
            isq[idx] = (dg > 0) ? rsqrtf((float)dg) : 0.0f;
            inv[idx] = (dg > 0) ? 1.0f / (float)dg : 0.0f;
            run += dg;
        }
    }
}

__global__ void k_fill(const int* __restrict__ eu, const int* __restrict__ ei) {
    int e = blockIdx.x * blockDim.x + threadIdx.x;
    if (e < NE) {
        int u = eu[e], it = ei[e];
        int pu = atomicAdd(&d_curu[u], 1);
        d_colu[pu] = it;
        int pi = atomicAdd(&d_curi[it], 1);
        d_coli[pi] = u;
    }
}

// ---------------- prescale: Xh = fp16(X * dv_isqrt) (layer 0; layers 1-2 fused into k_layer) ----------------
__global__ void k_prescale() {
    int gt = blockIdx.x * blockDim.x + threadIdx.x;
    if (gt < NV * 16) {
        int r = gt >> 4;
        float s = (r < NU) ? d_du_isqrt[r] : d_di_isqrt[r - NU];
        float4 x = ((const float4*)d_X)[gt];
        x.x *= s; x.y *= s; x.z *= s; x.w *= s;
        d_Xh[gt] = f4_to_h4(x);
    }
}

// ---------------- smoothing pass 1 (half-warp per vertex, fp16 rows) ----------------
// items: Sh[v]    = fp16( di_inv[v] * sum_{u in coli[v]} Xh[u] )
// users: Sh[NI+v] = fp16( du_inv[v] * sum_{i in colu[v]} Xh[NU+i] )
__global__ void k_smoothA() {
    int gt = blockIdx.x * blockDim.x + threadIdx.x;
    int hw = gt >> 4, lane = gt & 15;

    int v, s, e, base; float sc; int outr;
    if (hw < NI) {
        v = hw; s = d_rpi[v]; e = d_rpi[v + 1];
        base = 0; sc = d_di_inv[v]; outr = v;
        const int* __restrict__ col = d_coli;
        float4 a0 = {0,0,0,0}, a1 = {0,0,0,0}, a2 = {0,0,0,0}, a3 = {0,0,0,0};
        int p = s;
        for (; p + 3 < e; p += 4) {
            int n0 = __ldg(&col[p]);
            int n1 = __ldg(&col[p + 1]);
            int n2 = __ldg(&col[p + 2]);
            int n3 = __ldg(&col[p + 3]);
            float4 x0 = h4_to_f4(__ldg(&d_Xh[(base + n0) * 16 + lane]));
            float4 x1 = h4_to_f4(__ldg(&d_Xh[(base + n1) * 16 + lane]));
            float4 x2 = h4_to_f4(__ldg(&d_Xh[(base + n2) * 16 + lane]));
            float4 x3 = h4_to_f4(__ldg(&d_Xh[(base + n3) * 16 + lane]));
            a0.x += x0.x; a0.y += x0.y; a0.z += x0.z; a0.w += x0.w;
            a1.x += x1.x; a1.y += x1.y; a1.z += x1.z; a1.w += x1.w;
            a2.x += x2.x; a2.y += x2.y; a2.z += x2.z; a2.w += x2.w;
            a3.x += x3.x; a3.y += x3.y; a3.z += x3.z; a3.w += x3.w;
        }
        for (; p < e; p++) {
            int n0 = __ldg(&col[p]);
            float4 x0 = h4_to_f4(__ldg(&d_Xh[(base + n0) * 16 + lane]));
            a0.x += x0.x; a0.y += x0.y; a0.z += x0.z; a0.w += x0.w;
        }
        float4 o;
        o.x = sc * (a0.x + a1.x + a2.x + a3.x);
        o.y = sc * (a0.y + a1.y + a2.y + a3.y);
        o.z = sc * (a0.z + a1.z + a2.z + a3.z);
        o.w = sc * (a0.w + a1.w + a2.w + a3.w);
        d_Sh[outr * 16 + lane] = f4_to_h4(o);
    } else if (hw < NV) {
        v = hw - NI; s = d_rpu[v]; e = d_rpu[v + 1];
        base = NU; sc = d_du_inv[v]; outr = NI + v;
        const int* __restrict__ col = d_colu;
        float4 a0 = {0,0,0,0}, a1 = {0,0,0,0}, a2 = {0,0,0,0}, a3 = {0,0,0,0};
        int p = s;
        for (; p + 3 < e; p += 4) {
            int n0 = __ldg(&col[p]);
            int n1 = __ldg(&col[p + 1]);
            int n2 = __ldg(&col[p + 2]);
            int n3 = __ldg(&col[p + 3]);
            float4 x0 = h4_to_f4(__ldg(&d_Xh[(base + n0) * 16 + lane]));
            float4 x1 = h4_to_f4(__ldg(&d_Xh[(base + n1) * 16 + lane]));
            float4 x2 = h4_to_f4(__ldg(&d_Xh[(base + n2) * 16 + lane]));
            float4 x3 = h4_to_f4(__ldg(&d_Xh[(base + n3) * 16 + lane]));
            a0.x += x0.x; a0.y += x0.y; a0.z += x0.z; a0.w += x0.w;
            a1.x += x1.x; a1.y += x1.y; a1.z += x1.z; a1.w += x1.w;
            a2.x += x2.x; a2.y += x2.y; a2.z += x2.z; a2.w += x2.w;
            a3.x += x3.x; a3.y += x3.y; a3.z += x3.z; a3.w += x3.w;
        }
        for (; p < e; p++) {
            int n0 = __ldg(&col[p]);
            float4 x0 = h4_to_f4(__ldg(&d_Xh[(base + n0) * 16 + lane]));
            a0.x += x0.x; a0.y += x0.y; a0.z += x0.z; a0.w += x0.w;
        }
        float4 o;
        o.x = sc * (a0.x + a1.x + a2.x + a3.x);
        o.y = sc * (a0.y + a1.y + a2.y + a3.y);
        o.z = sc * (a0.z + a1.z + a2.z + a3.z);
        o.w = sc * (a0.w + a1.w + a2.w + a3.w);
        d_Sh[outr * 16 + lane] = f4_to_h4(o);
    }
}

// ---------------- smoothing pass 2: g (fp32) from Sh ----------------
// users: g[v]    = du_isqrt[v] * sum_{i in colu[v]} Sh[i]
// items: g[NU+v] = di_isqrt[v] * sum_{u in coli[v]} Sh[NI+u]
__global__ void k_smoothB() {
    int gt = blockIdx.x * blockDim.x + threadIdx.x;
    int hw = gt >> 4, lane = gt & 15;
    float4* __restrict__ G4 = (float4*)d_g;

    if (hw < NU) {
        int v = hw;
        int s = d_rpu[v], e = d_rpu[v + 1];
        const int* __restrict__ col = d_colu;
        float4 a0 = {0,0,0,0}, a1 = {0,0,0,0}, a2 = {0,0,0,0}, a3 = {0,0,0,0};
        int p = s;
        for (; p + 3 < e; p += 4) {
            int n0 = __ldg(&col[p]);
            int n1 = __ldg(&col[p + 1]);
            int n2 = __ldg(&col[p + 2]);
            int n3 = __ldg(&col[p + 3]);
            float4 x0 = h4_to_f4(__ldg(&d_Sh[n0 * 16 + lane]));
            float4 x1 = h4_to_f4(__ldg(&d_Sh[n1 * 16 + lane]));
            float4 x2 = h4_to_f4(__ldg(&d_Sh[n2 * 16 + lane]));
            float4 x3 = h4_to_f4(__ldg(&d_Sh[n3 * 16 + lane]));
            a0.x += x0.x; a0.y += x0.y; a0.z += x0.z; a0.w += x0.w;
            a1.x += x1.x; a1.y += x1.y; a1.z += x1.z; a1.w += x1.w;
            a2.x += x2.x; a2.y += x2.y; a2.z += x2.z; a2.w += x2.w;
            a3.x += x3.x; a3.y += x3.y; a3.z += x3.z; a3.w += x3.w;
        }
        for (; p < e; p++) {
            int n0 = __ldg(&col[p]);
            float4 x0 = h4_to_f4(__ldg(&d_Sh[n0 * 16 + lane]));
            a0.x += x0.x; a0.y += x0.y; a0.z += x0.z; a0.w += x0.w;
        }
        float sc = d_du_isqrt[v];
        float4 o;
        o.x = sc * (a0.x + a1.x + a2.x + a3.x);
        o.y = sc * (a0.y + a1.y + a2.y + a3.y);
        o.z = sc * (a0.z + a1.z + a2.z + a3.z);
        o.w = sc * (a0.w + a1.w + a2.w + a3.w);
        G4[v * 16 + lane] = o;
    } else if (hw < NV) {
        int v = hw - NU;
        int s = d_rpi[v], e = d_rpi[v + 1];
        const int* __restrict__ col = d_coli;
        float4 a0 = {0,0,0,0}, a1 = {0,0,0,0}, a2 = {0,0,0,0}, a3 = {0,0,0,0};
        int p = s;
        for (; p + 3 < e; p += 4) {
            int n0 = __ldg(&col[p]);
            int n1 = __ldg(&col[p + 1]);
            int n2 = __ldg(&col[p + 2]);
            int n3 = __ldg(&col[p + 3]);
            float4 x0 = h4_to_f4(__ldg(&d_Sh[(NI + n0) * 16 + lane]));
            float4 x1 = h4_to_f4(__ldg(&d_Sh[(NI + n1) * 16 + lane]));
            float4 x2 = h4_to_f4(__ldg(&d_Sh[(NI + n2) * 16 + lane]));
            float4 x3 = h4_to_f4(__ldg(&d_Sh[(NI + n3) * 16 + lane]));
            a0.x += x0.x; a0.y += x0.y; a0.z += x0.z; a0.w += x0.w;
            a1.x += x1.x; a1.y += x1.y; a1.z += x1.z; a1.w += x1.w;
            a2.x += x2.x; a2.y += x2.y; a2.z += x2.z; a2.w += x2.w;
            a3.x += x3.x; a3.y += x3.y; a3.z += x3.z; a3.w += x3.w;
        }
        for (; p < e; p++) {
            int n0 = __ldg(&col[p]);
            float4 x0 = h4_to_f4(__ldg(&d_Sh[(NI + n0) * 16 + lane]));
            a0.x += x0.x; a0.y += x0.y; a0.z += x0.z; a0.w += x0.w;
        }
        float sc = d_di_isqrt[v];
        float4 o;
        o.x = sc * (a0.x + a1.x + a2.x + a3.x);
        o.y = sc * (a0.y + a1.y + a2.y + a3.y);
        o.z = sc * (a0.z + a1.z + a2.z + a3.z);
        o.w = sc * (a0.w + a1.w + a2.w + a3.w);
        G4[(NU + v) * 16 + lane] = o;
    }
}

// ---------------- fused layer update ----------------
#define SMEM_FLOATS (4160 + 4160 + 4096 + 4096 + 64 + 64)
__global__ void k_layer(const float* __restrict__ Wgc, const float* __restrict__ bgc,
                        const float* __restrict__ Wbi, const float* __restrict__ bbi,
                        int l, int write_xs) {
    extern __shared__ float sh[];
    float* sG  = sh;              // [64][65]
    float* sX  = sh + 4160;       // [64][65]
    float* sWg = sh + 8320;       // Wt[k][d]
    float* sWb = sh + 12416;
    float* sbg = sh + 16512;
    float* sbb = sh + 16576;

    int t = threadIdx.x;          // 256 threads
    int row0 = blockIdx.x * 64;

    const float* Wg = Wgc + l * 4096;
    const float* Wb = Wbi + l * 4096;
    #pragma unroll
    for (int i = t; i < 4096; i += 256) {
        int k = i >> 6, d = i & 63;
        sWg[k * 64 + d] = __ldg(&Wg[d * 64 + k]);
        sWb[k * 64 + d] = __ldg(&Wb[d * 64 + k]);
    }
    if (t < 64) {
        sbg[t] = bgc[l * 64 + t];
        sbb[t] = bbi[l * 64 + t];
    }
    #pragma unroll
    for (int i = t; i < 4096; i += 256) {
        int r = i >> 6, k = i & 63;
        int gr = row0 + r;
        float gv = 0.f, xv = 0.f;
        if (gr < NV) { gv = d_g[gr * 64 + k]; xv = d_X[gr * 64 + k]; }
        sG[r * 65 + k] = gv;
        sX[r * 65 + k] = xv;
    }
    __syncthreads();

    int tx = t & 15, ty = t >> 4;
    int c0 = tx * 4, r0 = ty * 4;
    float ag[4][4] = {}, ab[4][4] = {};

    #pragma unroll 8
    for (int k = 0; k < 64; k++) {
        float4 wg = *(const float4*)&sWg[k * 64 + c0];
        float4 wb = *(const float4*)&sWb[k * 64 + c0];
        #pragma unroll
        for (int i = 0; i < 4; i++) {
            float gv = sG[(r0 + i) * 65 + k];
            float xv = sX[(r0 + i) * 65 + k];
            float hv = gv * xv;
            ag[i][0] += gv * wg.x; ag[i][1] += gv * wg.y; ag[i][2] += gv * wg.z; ag[i][3] += gv * wg.w;
            ab[i][0] += hv * wb.x; ab[i][1] += hv * wb.y; ab[i][2] += hv * wb.z; ab[i][3] += hv * wb.w;
        }
    }

    #pragma unroll
    for (int i = 0; i < 4; i++) {
        float vj[4];
        float ssq = 0.f;
        #pragma unroll
        for (int j = 0; j < 4; j++) {
            float sg = ag[i][j] + sbg[c0 + j] + sX[(r0 + i) * 65 + (c0 + j)];
            sg = (sg > 0.f) ? sg : 0.2f * sg;
            float sb = ab[i][j] + sbb[c0 + j];
            sb = (sb > 0.f) ? sb : 0.2f * sb;
            float v = sg + sb;
            vj[j] = v;
            ssq += v * v;
        }
        #pragma unroll
        for (int m = 8; m >= 1; m >>= 1)
            ssq += __shfl_xor_sync(0xffffffffu, ssq, m);
        float inv = 1.0f / fmaxf(sqrtf(ssq), 1e-12f);
        int gr = row0 + r0 + i;
        if (gr < NV) {
            float4 o;
            o.x = vj[0] * inv; o.y = vj[1] * inv; o.z = vj[2] * inv; o.w = vj[3] * inv;
            *(float4*)&d_X[gr * 64 + c0] = o;
            float4 a = *(float4*)&d_acc[gr * 64 + c0];
            a.x += o.x; a.y += o.y; a.z += o.z; a.w += o.w;
            *(float4*)&d_acc[gr * 64 + c0] = a;
            if (write_xs) {
                float srow = (gr < NU) ? d_du_isqrt[gr] : d_di_isqrt[gr - NU];
                float4 xs;
                xs.x = o.x * srow; xs.y = o.y * srow; xs.z = o.z * srow; xs.w = o.w * srow;
                d_Xh[gr * 16 + (c0 >> 2)] = f4_to_h4(xs);
            }
        }
    }
}

__global__ void k_out(float* __restrict__ out) {
    int idx = blockIdx.x * blockDim.x + threadIdx.x;
    if (idx < NV * D) out[idx] = d_acc[idx] * 0.25f;
}

// ---------------- launch ----------------
extern "C" void kernel_launch(void* const* d_in, const int* in_sizes, int n_in,
                              void* d_out, int out_size) {
    const float* u_emb = (const float*)d_in[0];
    const float* i_emb = (const float*)d_in[1];
    const float* Wgc   = (const float*)d_in[2];
    const float* bgc   = (const float*)d_in[3];
    const float* Wbi   = (const float*)d_in[4];
    const float* bbi   = (const float*)d_in[5];
    const int*   eu    = (const int*)d_in[6];
    const int*   ei    = (const int*)d_in[7];
    float* out = (float*)d_out;

    cudaFuncSetAttribute(k_layer, cudaFuncAttributeMaxDynamicSharedMemorySize,
                         SMEM_FLOATS * (int)sizeof(float));

    k_init<<<(NV * D + 255) / 256, 256>>>(u_emb, i_emb);
    k_degree<<<(NE + 255) / 256, 256>>>(eu, ei);
    k_part<<<NPART, 256>>>();
    k_spine<<<1, 256>>>();
    k_down<<<NPART, 256>>>();
    k_fill<<<(NE + 255) / 256, 256>>>(eu, ei);
    k_prescale<<<(NV * 16 + 255) / 256, 256>>>();

    for (int l = 0; l < NL; l++) {
        k_smoothA<<<(NV * 16 + 255) / 256, 256>>>();
        k_smoothB<<<(NV * 16 + 255) / 256, 256>>>();
        k_layer<<<(NV + 63) / 64, 256, SMEM_FLOATS * (int)sizeof(float)>>>(
            Wgc, bgc, Wbi, bbi, l, (l < NL - 1) ? 1 : 0);
    }

    k_out<<<(NV * D + 255) / 256, 256>>>(out);
}

// round 4
// speedup vs baseline: 1.5842x; 1.4105x over previous
#include <cuda_runtime.h>
#include <cuda_fp16.h>
#include <mma.h>

using namespace nvcuda;

#define NU 100000
#define NI 50000
#define NV 150000
#define D  64
#define NE 1000000
#define NL 3

#define CHUNK 1024
#define PBU ((NU + CHUNK - 1) / CHUNK)   // 98
#define PBI ((NI + CHUNK - 1) / CHUNK)   // 49
#define NPART (PBU + PBI)                // 147

// ---------------- static device scratch ----------------
__device__ float d_X[NV * D];     // current layer embeddings [users; items] (fp32)
__device__ float d_acc[NV * D];   // running sum of layer embeddings
__device__ uint2 d_gh[NV * 16];   // smoothed embeddings g (fp16 rows)
__device__ uint2 d_Xh[NV * 16];   // X pre-scaled by dv_isqrt, fp16 rows
__device__ uint2 d_Sh[NV * 16];   // mid-hop scratch fp16: E(items) [0..NI), F(users) [NI..NV)
__device__ int   d_deg_u[NU], d_deg_i[NI];
__device__ float d_du_isqrt[NU], d_du_inv[NU];
__device__ float d_di_isqrt[NI], d_di_inv[NI];
__device__ int   d_rpu[NU + 1], d_rpi[NI + 1];
__device__ int   d_curu[NU], d_curi[NI];
__device__ int   d_colu[NE];      // items, grouped by user
__device__ int   d_coli[NE];      // users, grouped by item
__device__ int   d_part[256];

// ---------------- helpers ----------------
__device__ __forceinline__ float4 h4_to_f4(uint2 q) {
    __half2 h0 = *(__half2*)&q.x;
    __half2 h1 = *(__half2*)&q.y;
    float2 f0 = __half22float2(h0);
    float2 f1 = __half22float2(h1);
    return make_float4(f0.x, f0.y, f1.x, f1.y);
}
__device__ __forceinline__ uint2 f4_to_h4(float4 f) {
    __half2 h0 = __floats2half2_rn(f.x, f.y);
    __half2 h1 = __floats2half2_rn(f.z, f.w);
    uint2 q;
    q.x = *(unsigned*)&h0;
    q.y = *(unsigned*)&h1;
    return q;
}

// ---------------- init ----------------
__global__ void k_init(const float* __restrict__ u_emb, const float* __restrict__ i_emb) {
    int idx = blockIdx.x * blockDim.x + threadIdx.x;
    if (idx < NV * D) {
        float v = (idx < NU * D) ? u_emb[idx] : i_emb[idx - NU * D];
        d_X[idx] = v;
        d_acc[idx] = v;
    }
    if (idx < NU) d_deg_u[idx] = 0;
    if (idx < NI) d_deg_i[idx] = 0;
}

__global__ void k_degree(const int* __restrict__ eu, const int* __restrict__ ei) {
    int e = blockIdx.x * blockDim.x + threadIdx.x;
    if (e < NE) {
        atomicAdd(&d_deg_u[eu[e]], 1);
        atomicAdd(&d_deg_i[ei[e]], 1);
    }
}

// ---------------- 3-phase scan ----------------
__global__ void k_part() {
    int b = blockIdx.x;
    const int* deg; int n; int cb;
    if (b < PBU) { deg = d_deg_u; n = NU; cb = b; }
    else         { deg = d_deg_i; n = NI; cb = b - PBU; }
    int base = cb * CHUNK;
    int t = threadIdx.x;
    int tsum = 0;
    #pragma unroll
    for (int j = 0; j < 4; j++) {
        int idx = base + t * 4 + j;
        if (idx < n) tsum += deg[idx];
    }
    #pragma unroll
    for (int m = 16; m >= 1; m >>= 1) tsum += __shfl_xor_sync(0xffffffffu, tsum, m);
    __shared__ int sw[8];
    if ((t & 31) == 0) sw[t >> 5] = tsum;
    __syncthreads();
    if (t == 0) {
        int s = 0;
        #pragma unroll
        for (int w = 0; w < 8; w++) s += sw[w];
        d_part[b] = s;
    }
}

__global__ void k_spine() {
    __shared__ int s[256];
    int t = threadIdx.x;
    int v = (t < NPART) ? d_part[t] : 0;
    s[t] = v;
    __syncthreads();
    #pragma unroll
    for (int off = 1; off < 256; off <<= 1) {
        int add = 0;
        if (t >= off && (((t - off) >= PBU) == (t >= PBU))) add = s[t - off];
        __syncthreads();
        s[t] += add;
        __syncthreads();
    }
    if (t < NPART) d_part[t] = s[t] - v;
    if (t == PBU - 1)   d_rpu[NU] = s[t];
    if (t == NPART - 1) d_rpi[NI] = s[t];
}

__global__ void k_down() {
    int b = blockIdx.x;
    const int* deg; int* rp; int* cur; float* isq; float* inv; int n; int cb;
    if (b < PBU) { deg = d_deg_u; rp = d_rpu; cur = d_curu; isq = d_du_isqrt; inv = d_du_inv; n = NU; cb = b; }
    else         { deg = d_deg_i; rp = d_rpi; cur = d_curi; isq = d_di_isqrt; inv = d_di_inv; n = NI; cb = b - PBU; }
    int base = cb * CHUNK;
    int t = threadIdx.x;
    int idx0 = base + t * 4;
    int v[4]; int tsum = 0;
    #pragma unroll
    for (int j = 0; j < 4; j++) {
        v[j] = (idx0 + j < n) ? deg[idx0 + j] : 0;
        tsum += v[j];
    }
    __shared__ int s[256];
    s[t] = tsum;
    __syncthreads();
    #pragma unroll
    for (int off = 1; off < 256; off <<= 1) {
        int add = (t >= off) ? s[t - off] : 0;
        __syncthreads();
        s[t] += add;
        __syncthreads();
    }
    int off0 = d_part[b] + (s[t] - tsum);
    int run = 0;
    #pragma unroll
    for (int j = 0; j < 4; j++) {
        int idx = idx0 + j;
        if (idx < n) {
            rp[idx] = off0 + run;
            cur[idx] = off0 + run;
            int dg = v[j];
            isq[idx] = (dg > 0) ? rsqrtf((float)dg) : 0.0f;
            inv[idx] = (dg > 0) ? 1.0f / (float)dg : 0.0f;
            run += dg;
        }
    }
}

__global__ void k_fill(const int* __restrict__ eu, const int* __restrict__ ei) {
    int e = blockIdx.x * blockDim.x + threadIdx.x;
    if (e < NE) {
        int u = eu[e], it = ei[e];
        int pu = atomicAdd(&d_curu[u], 1);
        d_colu[pu] = it;
        int pi = atomicAdd(&d_curi[it], 1);
        d_coli[pi] = u;
    }
}

// ---------------- prescale: Xh = fp16(X * dv_isqrt) (layer 0) ----------------
__global__ void k_prescale() {
    int gt = blockIdx.x * blockDim.x + threadIdx.x;
    if (gt < NV * 16) {
        int r = gt >> 4;
        float s = (r < NU) ? d_du_isqrt[r] : d_di_isqrt[r - NU];
        float4 x = ((const float4*)d_X)[gt];
        x.x *= s; x.y *= s; x.z *= s; x.w *= s;
        d_Xh[gt] = f4_to_h4(x);
    }
}

// ---------------- smoothing pass 1 (half-warp per vertex, fp16 rows) ----------------
__global__ void k_smoothA() {
    int gt = blockIdx.x * blockDim.x + threadIdx.x;
    int hw = gt >> 4, lane = gt & 15;

    if (hw < NI) {
        int v = hw;
        int s = d_rpi[v], e = d_rpi[v + 1];
        const int* __restrict__ col = d_coli;
        float4 a0 = {0,0,0,0}, a1 = {0,0,0,0}, a2 = {0,0,0,0}, a3 = {0,0,0,0};
        int p = s;
        for (; p + 3 < e; p += 4) {
            int n0 = __ldg(&col[p]);
            int n1 = __ldg(&col[p + 1]);
            int n2 = __ldg(&col[p + 2]);
            int n3 = __ldg(&col[p + 3]);
            float4 x0 = h4_to_f4(__ldg(&d_Xh[n0 * 16 + lane]));
            float4 x1 = h4_to_f4(__ldg(&d_Xh[n1 * 16 + lane]));
            float4 x2 = h4_to_f4(__ldg(&d_Xh[n2 * 16 + lane]));
            float4 x3 = h4_to_f4(__ldg(&d_Xh[n3 * 16 + lane]));
            a0.x += x0.x; a0.y += x0.y; a0.z += x0.z; a0.w += x0.w;
            a1.x += x1.x; a1.y += x1.y; a1.z += x1.z; a1.w += x1.w;
            a2.x += x2.x; a2.y += x2.y; a2.z += x2.z; a2.w += x2.w;
            a3.x += x3.x; a3.y += x3.y; a3.z += x3.z; a3.w += x3.w;
        }
        for (; p < e; p++) {
            int n0 = __ldg(&col[p]);
            float4 x0 = h4_to_f4(__ldg(&d_Xh[n0 * 16 + lane]));
            a0.x += x0.x; a0.y += x0.y; a0.z += x0.z; a0.w += x0.w;
        }
        float sc = d_di_inv[v];
        float4 o;
        o.x = sc * (a0.x + a1.x + a2.x + a3.x);
        o.y = sc * (a0.y + a1.y + a2.y + a3.y);
        o.z = sc * (a0.z + a1.z + a2.z + a3.z);
        o.w = sc * (a0.w + a1.w + a2.w + a3.w);
        d_Sh[v * 16 + lane] = f4_to_h4(o);
    } else if (hw < NV) {
        int v = hw - NI;
        int s = d_rpu[v], e = d_rpu[v + 1];
        const int* __restrict__ col = d_colu;
        float4 a0 = {0,0,0,0}, a1 = {0,0,0,0}, a2 = {0,0,0,0}, a3 = {0,0,0,0};
        int p = s;
        for (; p + 3 < e; p += 4) {
            int n0 = __ldg(&col[p]);
            int n1 = __ldg(&col[p + 1]);
            int n2 = __ldg(&col[p + 2]);
            int n3 = __ldg(&col[p + 3]);
            float4 x0 = h4_to_f4(__ldg(&d_Xh[(NU + n0) * 16 + lane]));
            float4 x1 = h4_to_f4(__ldg(&d_Xh[(NU + n1) * 16 + lane]));
            float4 x2 = h4_to_f4(__ldg(&d_Xh[(NU + n2) * 16 + lane]));
            float4 x3 = h4_to_f4(__ldg(&d_Xh[(NU + n3) * 16 + lane]));
            a0.x += x0.x; a0.y += x0.y; a0.z += x0.z; a0.w += x0.w;
            a1.x += x1.x; a1.y += x1.y; a1.z += x1.z; a1.w += x1.w;
            a2.x += x2.x; a2.y += x2.y; a2.z += x2.z; a2.w += x2.w;
            a3.x += x3.x; a3.y += x3.y; a3.z += x3.z; a3.w += x3.w;
        }
        for (; p < e; p++) {
            int n0 = __ldg(&col[p]);
            float4 x0 = h4_to_f4(__ldg(&d_Xh[(NU + n0) * 16 + lane]));
            a0.x += x0.x; a0.y += x0.y; a0.z += x0.z; a0.w += x0.w;
        }
        float sc = d_du_inv[v];
        float4 o;
        o.x = sc * (a0.x + a1.x + a2.x + a3.x);
        o.y = sc * (a0.y + a1.y + a2.y + a3.y);
        o.z = sc * (a0.z + a1.z + a2.z + a3.z);
        o.w = sc * (a0.w + a1.w + a2.w + a3.w);
        d_Sh[(NI + v) * 16 + lane] = f4_to_h4(o);
    }
}

// ---------------- smoothing pass 2: g (fp16) from Sh ----------------
__global__ void k_smoothB() {
    int gt = blockIdx.x * blockDim.x + threadIdx.x;
    int hw = gt >> 4, lane = gt & 15;

    if (hw < NU) {
        int v = hw;
        int s = d_rpu[v], e = d_rpu[v + 1];
        const int* __restrict__ col = d_colu;
        float4 a0 = {0,0,0,0}, a1 = {0,0,0,0}, a2 = {0,0,0,0}, a3 = {0,0,0,0};
        int p = s;
        for (; p + 3 < e; p += 4) {
            int n0 = __ldg(&col[p]);
            int n1 = __ldg(&col[p + 1]);
            int n2 = __ldg(&col[p + 2]);
            int n3 = __ldg(&col[p + 3]);
            float4 x0 = h4_to_f4(__ldg(&d_Sh[n0 * 16 + lane]));
            float4 x1 = h4_to_f4(__ldg(&d_Sh[n1 * 16 + lane]));
            float4 x2 = h4_to_f4(__ldg(&d_Sh[n2 * 16 + lane]));
            float4 x3 = h4_to_f4(__ldg(&d_Sh[n3 * 16 + lane]));
            a0.x += x0.x; a0.y += x0.y; a0.z += x0.z; a0.w += x0.w;
            a1.x += x1.x; a1.y += x1.y; a1.z += x1.z; a1.w += x1.w;
            a2.x += x2.x; a2.y += x2.y; a2.z += x2.z; a2.w += x2.w;
            a3.x += x3.x; a3.y += x3.y; a3.z += x3.z; a3.w += x3.w;
        }
        for (; p < e; p++) {
            int n0 = __ldg(&col[p]);
            float4 x0 = h4_to_f4(__ldg(&d_Sh[n0 * 16 + lane]));
            a0.x += x0.x; a0.y += x0.y; a0.z += x0.z; a0.w += x0.w;
        }
        float sc = d_du_isqrt[v];
        float4 o;
        o.x = sc * (a0.x + a1.x + a2.x + a3.x);
        o.y = sc * (a0.y + a1.y + a2.y + a3.y);
        o.z = sc * (a0.z + a1.z + a2.z + a3.z);
        o.w = sc * (a0.w + a1.w + a2.w + a3.w);
        d_gh[v * 16 + lane] = f4_to_h4(o);
    } else if (hw < NV) {
        int v = hw - NU;
        int s = d_rpi[v], e = d_rpi[v + 1];
        const int* __restrict__ col = d_coli;
        float4 a0 = {0,0,0,0}, a1 = {0,0,0,0}, a2 = {0,0,0,0}, a3 = {0,0,0,0};
        int p = s;
        for (; p + 3 < e; p += 4) {
            int n0 = __ldg(&col[p]);
            int n1 = __ldg(&col[p + 1]);
            int n2 = __ldg(&col[p + 2]);
            int n3 = __ldg(&col[p + 3]);
            float4 x0 = h4_to_f4(__ldg(&d_Sh[(NI + n0) * 16 + lane]));
            float4 x1 = h4_to_f4(__ldg(&d_Sh[(NI + n1) * 16 + lane]));
            float4 x2 = h4_to_f4(__ldg(&d_Sh[(NI + n2) * 16 + lane]));
            float4 x3 = h4_to_f4(__ldg(&d_Sh[(NI + n3) * 16 + lane]));
            a0.x += x0.x; a0.y += x0.y; a0.z += x0.z; a0.w += x0.w;
            a1.x += x1.x; a1.y += x1.y; a1.z += x1.z; a1.w += x1.w;
            a2.x += x2.x; a2.y += x2.y; a2.z += x2.z; a2.w += x2.w;
            a3.x += x3.x; a3.y += x3.y; a3.z += x3.z; a3.w += x3.w;
        }
        for (; p < e; p++) {
            int n0 = __ldg(&col[p]);
            float4 x0 = h4_to_f4(__ldg(&d_Sh[(NI + n0) * 16 + lane]));
            a0.x += x0.x; a0.y += x0.y; a0.z += x0.z; a0.w += x0.w;
        }
        float sc = d_di_isqrt[v];
        float4 o;
        o.x = sc * (a0.x + a1.x + a2.x + a3.x);
        o.y = sc * (a0.y + a1.y + a2.y + a3.y);
        o.z = sc * (a0.z + a1.z + a2.z + a3.z);
        o.w = sc * (a0.w + a1.w + a2.w + a3.w);
        d_gh[(NU + v) * 16 + lane] = f4_to_h4(o);
    }
}

// ---------------- fused layer update (tensor-core fp16 wmma) ----------------
// Cg = G @ Wgc^T, Cb = (X*G) @ Wbi^T  (fp16 in, fp32 acc)
// out_g = leaky(Cg + bgc + X); out_b = leaky(Cb + bbi)
// Xn = normalize(out_g + out_b); X = Xn; acc += Xn; Xh = fp16(Xn * dv_isqrt)
#define LDH 72   // half stride for G/H/W tiles
#define LDF 68   // float stride for X/C tiles
#define OFF_G   0
#define OFF_H   (OFF_G + 64 * LDH)            // halves
#define OFF_WG  (OFF_H + 64 * LDH)
#define OFF_WB  (OFF_WG + 64 * LDH)
#define HALves_TOTAL (OFF_WB + 64 * LDH)
#define OFF_X   0                              // floats, after half region
#define OFF_CG  (OFF_X + 64 * LDF)
#define OFF_CB  (OFF_CG + 64 * LDF)
#define OFF_BG  (OFF_CB + 64 * LDF)
#define OFF_BB  (OFF_BG + 64)
#define FLOATS_TOTAL (OFF_BB + 64)
#define SMEM_BYTES (HALves_TOTAL * 2 + FLOATS_TOTAL * 4)

__global__ void k_layer(const float* __restrict__ Wgc, const float* __restrict__ bgc,
                        const float* __restrict__ Wbi, const float* __restrict__ bbi,
                        int l, int write_xs) {
    extern __shared__ __align__(16) char smraw[];
    __half* sH_base = (__half*)smraw;
    float*  sF_base = (float*)(smraw + HALves_TOTAL * 2);
    __half* sG  = sH_base + OFF_G;
    __half* sHm = sH_base + OFF_H;
    __half* sWg = sH_base + OFF_WG;
    __half* sWb = sH_base + OFF_WB;
    float*  sX  = sF_base + OFF_X;
    float*  sCg = sF_base + OFF_CG;
    float*  sCb = sF_base + OFF_CB;
    float*  sbg = sF_base + OFF_BG;
    float*  sbb = sF_base + OFF_BB;

    int t = threadIdx.x;          // 256 threads
    int row0 = blockIdx.x * 64;

    // --- stage weights (row-major W[d][k] == col-major B[k][d]) as fp16 ---
    const float* Wg = Wgc + l * 4096;
    const float* Wb = Wbi + l * 4096;
    #pragma unroll
    for (int i = t; i < 64 * 16; i += 256) {
        int dd = i >> 4, kq = i & 15;
        float4 wg4 = __ldg((const float4*)&Wg[dd * 64 + kq * 4]);
        float4 wb4 = __ldg((const float4*)&Wb[dd * 64 + kq * 4]);
        *(uint2*)&sWg[dd * LDH + kq * 4] = f4_to_h4(wg4);
        *(uint2*)&sWb[dd * LDH + kq * 4] = f4_to_h4(wb4);
    }
    if (t < 64) {
        sbg[t] = bgc[l * 64 + t];
        sbb[t] = bbi[l * 64 + t];
    }
    // --- stage G (fp16), X (fp32), H = X*G (fp16) ---
    #pragma unroll
    for (int i = t; i < 64 * 16; i += 256) {
        int r = i >> 4, kq = i & 15;
        int gr = row0 + r;
        uint2 gq = make_uint2(0u, 0u);
        float4 xq = make_float4(0.f, 0.f, 0.f, 0.f);
        if (gr < NV) {
            gq = d_gh[gr * 16 + kq];
            xq = ((const float4*)d_X)[gr * 16 + kq];
        }
        *(uint2*)&sG[r * LDH + kq * 4] = gq;
        *(float4*)&sX[r * LDF + kq * 4] = xq;
        float4 gf = h4_to_f4(gq);
        float4 hf;
        hf.x = gf.x * xq.x; hf.y = gf.y * xq.y; hf.z = gf.z * xq.z; hf.w = gf.w * xq.w;
        *(uint2*)&sHm[r * LDH + kq * 4] = f4_to_h4(hf);
    }
    __syncthreads();

    // --- wmma: 8 warps, warps 0-3 -> Cg n-strips, warps 4-7 -> Cb n-strips ---
    {
        int w = t >> 5;
        int sel = w >> 2;          // 0: Cg, 1: Cb
        int nt = w & 3;            // n-tile (16 cols)
        const __half* A = sel ? sHm : sG;
        const __half* B = sel ? sWb : sWg;
        float* C = sel ? sCb : sCg;

        wmma::fragment<wmma::accumulator, 16, 16, 16, float> acc[4];
        #pragma unroll
        for (int m = 0; m < 4; m++) wmma::fill_fragment(acc[m], 0.0f);

        #pragma unroll
        for (int k = 0; k < 4; k++) {
            wmma::fragment<wmma::matrix_b, 16, 16, 16, __half, wmma::col_major> bf;
            wmma::load_matrix_sync(bf, B + nt * 16 * LDH + k * 16, LDH);
            #pragma unroll
            for (int m = 0; m < 4; m++) {
                wmma::fragment<wmma::matrix_a, 16, 16, 16, __half, wmma::row_major> af;
                wmma::load_matrix_sync(af, A + m * 16 * LDH + k * 16, LDH);
                wmma::mma_sync(acc[m], af, bf, acc[m]);
            }
        }
        #pragma unroll
        for (int m = 0; m < 4; m++)
            wmma::store_matrix_sync(C + m * 16 * LDF + nt * 16, acc[m], LDF, wmma::mem_row_major);
    }
    __syncthreads();

    // --- epilogue: bias + leaky + residual + L2 norm + accumulate ---
    int tx = t & 15, ty = t >> 4;
    int c0 = tx * 4, r0 = ty * 4;

    #pragma unroll
    for (int i = 0; i < 4; i++) {
        float vj[4];
        float ssq = 0.f;
        #pragma unroll
        for (int j = 0; j < 4; j++) {
            float sg = sCg[(r0 + i) * LDF + c0 + j] + sbg[c0 + j] + sX[(r0 + i) * LDF + c0 + j];
            sg = (sg > 0.f) ? sg : 0.2f * sg;
            float sb = sCb[(r0 + i) * LDF + c0 + j] + sbb[c0 + j];
            sb = (sb > 0.f) ? sb : 0.2f * sb;
            float v = sg + sb;
            vj[j] = v;
            ssq += v * v;
        }
        #pragma unroll
        for (int m = 8; m >= 1; m >>= 1)
            ssq += __shfl_xor_sync(0xffffffffu, ssq, m);
        float inv = 1.0f / fmaxf(sqrtf(ssq), 1e-12f);
        int gr = row0 + r0 + i;
        if (gr < NV) {
            float4 o;
            o.x = vj[0] * inv; o.y = vj[1] * inv; o.z = vj[2] * inv; o.w = vj[3] * inv;
            *(float4*)&d_X[gr * 64 + c0] = o;
            float4 a = *(float4*)&d_acc[gr * 64 + c0];
            a.x += o.x; a.y += o.y; a.z += o.z; a.w += o.w;
            *(float4*)&d_acc[gr * 64 + c0] = a;
            if (write_xs) {
                float srow = (gr < NU) ? d_du_isqrt[gr] : d_di_isqrt[gr - NU];
                float4 xs;
                xs.x = o.x * srow; xs.y = o.y * srow; xs.z = o.z * srow; xs.w = o.w * srow;
                d_Xh[gr * 16 + (c0 >> 2)] = f4_to_h4(xs);
            }
        }
    }
}

__global__ void k_out(float* __restrict__ out) {
    int idx = blockIdx.x * blockDim.x + threadIdx.x;
    if (idx < NV * D) out[idx] = d_acc[idx] * 0.25f;
}

// ---------------- launch ----------------
extern "C" void kernel_launch(void* const* d_in, const int* in_sizes, int n_in,
                              void* d_out, int out_size) {
    const float* u_emb = (const float*)d_in[0];
    const float* i_emb = (const float*)d_in[1];
    const float* Wgc   = (const float*)d_in[2];
    const float* bgc   = (const float*)d_in[3];
    const float* Wbi   = (const float*)d_in[4];
    const float* bbi   = (const float*)d_in[5];
    const int*   eu    = (const int*)d_in[6];
    const int*   ei    = (const int*)d_in[7];
    float* out = (float*)d_out;

    cudaFuncSetAttribute(k_layer, cudaFuncAttributeMaxDynamicSharedMemorySize, SMEM_BYTES);

    k_init<<<(NV * D + 255) / 256, 256>>>(u_emb, i_emb);
    k_degree<<<(NE + 255) / 256, 256>>>(eu, ei);
    k_part<<<NPART, 256>>>();
    k_spine<<<1, 256>>>();
    k_down<<<NPART, 256>>>();
    k_fill<<<(NE + 255) / 256, 256>>>(eu, ei);
    k_prescale<<<(NV * 16 + 255) / 256, 256>>>();

    for (int l = 0; l < NL; l++) {
        k_smoothA<<<(NV * 16 + 255) / 256, 256>>>();
        k_smoothB<<<(NV * 16 + 255) / 256, 256>>>();
        k_layer<<<(NV + 63) / 64, 256, SMEM_BYTES>>>(
            Wgc, bgc, Wbi, bbi, l, (l < NL - 1) ? 1 : 0);
    }

    k_out<<<(NV * D + 255) / 256, 256>>>(out);
}